// round 14
// baseline (speedup 1.0000x reference)
#include <cuda_runtime.h>
#include <cuda_fp16.h>
#include <math.h>
#include <cstdint>

#define HH 384
#define CC 192
#define WSZ 8
#define SHIFTV 4
#define NHEADS 6
#define HDIM 32
#define NTOK 64
#define NWIN 2304
#define TT 147456

// -------- scratch (device globals) --------
__device__ __half g_q_h[NWIN*NHEADS*NTOK*HDIM];
__device__ __half g_k_h[NWIN*NHEADS*NTOK*HDIM];
__device__ __half g_v_h[NWIN*NHEADS*NTOK*HDIM];
__device__ __half g_ctx_h[TT*CC];
__device__ float g_xattn[TT*CC];
__device__ float g_h[TT*CC];
__device__ __half g_mid_h[TT*2*CC];
__device__ float g_mlp[TT*CC];
__device__ float g_rpb[NHEADS*NTOK*NTOK];
__device__ float g_btab[225*NHEADS];
// transposed fp16 weights [N, K] K-major
__device__ __half g_wtq[CC*CC];
__device__ __half g_wtk[CC*CC];
__device__ __half g_wtv[CC*CC];
__device__ __half g_wtp[CC*CC];
__device__ __half g_wt1[2*CC*CC];     // [384, 192]
__device__ __half g_wt2[CC*2*CC];     // [192, 384]

__device__ __forceinline__ uint32_t f2tf32(float x) {
    uint32_t r;
    asm("cvt.rna.tf32.f32 %0, %1;" : "=r"(r) : "f"(x));
    return r;
}
__device__ __forceinline__ void split_tf32(float x, uint32_t& hi, uint32_t& lo) {
    hi = f2tf32(x);
    lo = f2tf32(x - __uint_as_float(hi));
}
__device__ __forceinline__ uint32_t packh2(float lo, float hi) {
    __half2 h = __floats2half2_rn(lo, hi);
    return *reinterpret_cast<uint32_t*>(&h);
}

__device__ __forceinline__ void mma_tf32(float& d0, float& d1, float& d2, float& d3,
                                         uint32_t a0, uint32_t a1, uint32_t a2, uint32_t a3,
                                         uint32_t b0, uint32_t b1) {
    asm volatile(
        "mma.sync.aligned.m16n8k8.row.col.f32.tf32.tf32.f32 "
        "{%0,%1,%2,%3}, {%4,%5,%6,%7}, {%8,%9}, {%0,%1,%2,%3};"
        : "+f"(d0), "+f"(d1), "+f"(d2), "+f"(d3)
        : "r"(a0), "r"(a1), "r"(a2), "r"(a3), "r"(b0), "r"(b1));
}
__device__ __forceinline__ void mma_f16(float& d0, float& d1, float& d2, float& d3,
                                        uint32_t a0, uint32_t a1, uint32_t a2, uint32_t a3,
                                        uint32_t b0, uint32_t b1) {
    asm volatile(
        "mma.sync.aligned.m16n8k16.row.col.f32.f16.f16.f32 "
        "{%0,%1,%2,%3}, {%4,%5,%6,%7}, {%8,%9}, {%0,%1,%2,%3};"
        : "+f"(d0), "+f"(d1), "+f"(d2), "+f"(d3)
        : "r"(a0), "r"(a1), "r"(a2), "r"(a3), "r"(b0), "r"(b1));
}

// ======================= weight transpose -> fp16 =======================
__global__ void k_tr(const float* __restrict__ q, const float* __restrict__ k,
                     const float* __restrict__ v, const float* __restrict__ p,
                     const float* __restrict__ f1, const float* __restrict__ f2) {
    int i = blockIdx.x * 256 + threadIdx.x;
    if (i < 36864)        g_wtq[(i % 192) * 192 + i / 192] = __float2half_rn(q[i]);
    else if (i < 73728)  { int j = i - 36864;  g_wtk[(j % 192) * 192 + j / 192] = __float2half_rn(k[j]); }
    else if (i < 110592) { int j = i - 73728;  g_wtv[(j % 192) * 192 + j / 192] = __float2half_rn(v[j]); }
    else if (i < 147456) { int j = i - 110592; g_wtp[(j % 192) * 192 + j / 192] = __float2half_rn(p[j]); }
    else if (i < 221184) { int j = i - 147456; g_wt1[(j % 384) * 192 + j / 384] = __float2half_rn(f1[j]); }
    else if (i < 294912) { int j = i - 221184; g_wt2[(j % 192) * 384 + j / 192] = __float2half_rn(f2[j]); }
}

// ======================= CPB / RPB =======================
__device__ __forceinline__ float cpb_coord(float x) {
    x = x / 7.0f * 8.0f;
    float s = (x > 0.f) ? 1.f : ((x < 0.f) ? -1.f : 0.f);
    return s * log2f(fabsf(x) + 1.0f) / log2f(8.0f);
}
__global__ void k_cpb(const float* __restrict__ w1, const float* __restrict__ b1,
                      const float* __restrict__ w2) {
    int row = blockIdx.x;
    int hh = threadIdx.x;
    float t0 = cpb_coord((float)(row / 15) - 7.0f);
    float t1 = cpb_coord((float)(row % 15) - 7.0f);
    float hv = t0 * w1[hh] + t1 * w1[512 + hh] + b1[hh];
    hv = fmaxf(hv, 0.f);
    __shared__ float red[512];
    for (int nh = 0; nh < 6; nh++) {
        red[hh] = hv * w2[hh * 6 + nh];
        __syncthreads();
        for (int s = 256; s > 0; s >>= 1) {
            if (hh < s) red[hh] += red[hh + s];
            __syncthreads();
        }
        if (hh == 0) g_btab[row * 6 + nh] = red[0];
        __syncthreads();
    }
}
__global__ void k_rpb() {
    int idx = blockIdx.x * 256 + threadIdx.x;
    if (idx >= NHEADS * NTOK * NTOK) return;
    int nh = idx >> 12;
    int ij = idx & 4095;
    int i = ij >> 6, j = ij & 63;
    int rel = ((i >> 3) - (j >> 3) + 7) * 15 + ((i & 7) - (j & 7) + 7);
    float b = g_btab[rel * 6 + nh];
    g_rpb[idx] = 16.0f / (1.0f + __expf(-b));
}

// ======================= fp16 GEMM with ldmatrix fragments =======================
#define HSA 20
#define RES_B_OFF (6*128*HSA)
#define RES_U32   (6*128*HSA + 2*192*HSA)
#define STR_A0 0
#define STR_A1 (128*HSA)
#define STR_B0 (2*128*HSA)
#define STR_B1 (2*128*HSA + 192*HSA)
#define STR_U32 (2*128*HSA + 2*192*HSA)

template <int MODE>
__global__ void __launch_bounds__(256, 1) k_g(const float* __restrict__ Xin,
                                              const float* __restrict__ bias_q,
                                              const float* __restrict__ bias_v,
                                              const float* __restrict__ resid,
                                              const float* __restrict__ ln_g,
                                              const float* __restrict__ ln_b) {
    constexpr bool RES = (MODE == 0 || MODE == 2);
    constexpr int KD  = (MODE == 3) ? 384 : 192;
    constexpr int NW  = (MODE == 0) ? 3 : ((MODE == 2) ? 2 : 1);
    constexpr int SEQ = RES ? NW * 6 : KD / 32;

    extern __shared__ uint32_t smu[];
    uint32_t sb = (uint32_t)__cvta_generic_to_shared(smu);
    int tid = threadIdx.x;
    int wid = tid >> 5, lane = tid & 31;
    int qr = lane >> 2, qc = lane & 3;
    int tile = blockIdx.x;

    int rb = (wid & 1) * 64;
    int nb0 = (wid >> 1) * 48;

    uint32_t a_row = (uint32_t)(rb + (lane & 15));
    uint32_t a_cadd = (uint32_t)((lane >> 4) * 4);
    uint32_t b_row = (uint32_t)(nb0 + (lane & 7) + ((lane >> 4) & 1) * 8);
    uint32_t b_cadd = (uint32_t)(((lane >> 3) & 1) * 4);

    float acc[4][6][4];
#pragma unroll
    for (int mf = 0; mf < 4; mf++)
#pragma unroll
        for (int nf = 0; nf < 6; nf++)
#pragma unroll
            for (int t = 0; t < 4; t++) acc[mf][nf][t] = 0.f;

    uint4 br[3];
    auto LOADB = [&](const __half* Wt, int nrow_base, int kb) {
#pragma unroll
        for (int i = 0; i < 3; i++) {
            int idx = tid + i * 256;
            int row = idx >> 2, kq4 = idx & 3;
            br[i] = *(const uint4*)(Wt + (long)(nrow_base + row) * KD + kb * 32 + kq4 * 8);
        }
    };
    auto STOREB = [&](uint32_t* B) {
#pragma unroll
        for (int i = 0; i < 3; i++) {
            int idx = tid + i * 256;
            int row = idx >> 2, kq4 = idx & 3;
            *(uint4*)&B[row * HSA + kq4 * 4] = br[i];
        }
    };

    auto MMA_CHUNK = [&](uint32_t Aoff, uint32_t Boff) {
#pragma unroll
        for (int g = 0; g < 2; g++) {
            uint32_t kof = g * 8;
            uint32_t a[4][4];
#pragma unroll
            for (int mf = 0; mf < 4; mf++) {
                uint32_t ad = sb + 4u * (Aoff + (a_row + mf * 16) * HSA + kof + a_cadd);
                asm volatile("ldmatrix.sync.aligned.m8n8.x4.shared.b16 {%0,%1,%2,%3}, [%4];"
                    : "=r"(a[mf][0]), "=r"(a[mf][1]), "=r"(a[mf][2]), "=r"(a[mf][3])
                    : "r"(ad));
            }
            uint32_t b[6][2];
#pragma unroll
            for (int p = 0; p < 3; p++) {
                uint32_t bd = sb + 4u * (Boff + (b_row + p * 16) * HSA + kof + b_cadd);
                asm volatile("ldmatrix.sync.aligned.m8n8.x4.shared.b16 {%0,%1,%2,%3}, [%4];"
                    : "=r"(b[2*p][0]), "=r"(b[2*p][1]), "=r"(b[2*p+1][0]), "=r"(b[2*p+1][1])
                    : "r"(bd));
            }
#pragma unroll
            for (int nf = 0; nf < 6; nf++)
#pragma unroll
                for (int mf = 0; mf < 4; mf++)
                    mma_f16(acc[mf][nf][0], acc[mf][nf][1], acc[mf][nf][2], acc[mf][nf][3],
                            a[mf][0], a[mf][1], a[mf][2], a[mf][3], b[nf][0], b[nf][1]);
        }
    };

    auto EPI = [&](int w) {
        const float* bias;
        if (MODE == 0)      bias = (w == 0) ? bias_q : ((w == 1) ? nullptr : bias_v);
        else                bias = bias_q;
#pragma unroll
        for (int mf = 0; mf < 4; mf++) {
#pragma unroll
            for (int t = 0; t < 2; t++) {
                int rloc = rb + mf * 16 + qr + t * 8;
                long tau = (long)tile * 128 + rloc;
                int win = (int)(tau >> 6), n = (int)(tau & 63);
#pragma unroll
                for (int nf = 0; nf < 6; nf++) {
                    int cloc = nb0 + nf * 8 + qc * 2;
                    float vx = acc[mf][nf][t * 2 + 0];
                    float vy = acc[mf][nf][t * 2 + 1];
                    if (MODE == 0) {
                        if (bias) { vx += bias[cloc]; vy += bias[cloc + 1]; }
                        int head = cloc >> 5, d = cloc & 31;
                        long off = (((long)(win * 6 + head) * 64 + n) << 5) + d;
                        __half* dst = (w == 0) ? g_q_h : ((w == 1) ? g_k_h : g_v_h);
                        *(uint32_t*)(dst + off) = packh2(vx, vy);
                    } else if (MODE == 1) {
                        vx += bias[cloc]; vy += bias[cloc + 1];
                        int r0 = (win / 48) * 8 + (n >> 3) + SHIFTV; if (r0 >= HH) r0 -= HH;
                        int c0 = (win % 48) * 8 + (n & 7)  + SHIFTV; if (c0 >= HH) c0 -= HH;
                        float* dst = g_xattn + (long)(r0 * HH + c0) * CC + cloc;
                        *(float2*)dst = make_float2(vx, vy);
                    } else if (MODE == 2) {
                        int col = w * 192 + cloc;
                        vx += bias[col]; vy += bias[col + 1];
                        vx = 0.5f * vx * (1.0f + erff(vx * 0.70710678118654752f));
                        vy = 0.5f * vy * (1.0f + erff(vy * 0.70710678118654752f));
                        *(uint32_t*)(g_mid_h + tau * 384 + col) = packh2(vx, vy);
                    } else {
                        vx += bias[cloc]; vy += bias[cloc + 1];
                        float* dst = g_mlp + tau * CC + cloc;
                        *(float2*)dst = make_float2(vx, vy);
                    }
                }
            }
        }
        if (RES && w + 1 < NW) {
#pragma unroll
            for (int mf = 0; mf < 4; mf++)
#pragma unroll
                for (int nf = 0; nf < 6; nf++)
#pragma unroll
                    for (int t = 0; t < 4; t++) acc[mf][nf][t] = 0.f;
        }
    };

    if (RES) {
        if (MODE == 2) {
            // ---- fused LN1 + residual prologue: per-row LN of g_xattn, add hidden,
            //      write g_h fp32, stage fp16 A chunks in smem ----
            __half* smh = (__half*)smu;
            for (int rr = 0; rr < 16; rr++) {
                int row = wid * 16 + rr;
                long p = (long)tile * 128 + row;
                const float* xr = Xin + p * CC;       // g_xattn
                float v[6];
                float sum = 0.f;
#pragma unroll
                for (int i = 0; i < 6; i++) { v[i] = xr[lane + 32 * i]; sum += v[i]; }
#pragma unroll
                for (int o = 16; o > 0; o >>= 1) sum += __shfl_xor_sync(0xffffffffu, sum, o);
                float mu = sum * (1.0f / CC);
                float var = 0.f;
#pragma unroll
                for (int i = 0; i < 6; i++) { float d = v[i] - mu; var += d * d; }
#pragma unroll
                for (int o = 16; o > 0; o >>= 1) var += __shfl_xor_sync(0xffffffffu, var, o);
                float inv = rsqrtf(var * (1.0f / CC) + 1e-5f);
#pragma unroll
                for (int i = 0; i < 6; i++) {
                    int ch = lane + 32 * i;
                    float r = resid[p * CC + ch] + (v[i] - mu) * inv * ln_g[ch] + ln_b[ch];
                    g_h[p * CC + ch] = r;
                    smh[(i * 128 * HSA + row * HSA) * 2 + lane] = __float2half_rn(r);
                }
            }
        } else {
#pragma unroll
            for (int i = 0; i < 24; i++) {
                int idx = tid + i * 256;
                int ch = idx >> 10, t2 = idx & 1023;
                int row = t2 >> 3, kq = t2 & 7;
                long tau = (long)tile * 128 + row;
                int win = (int)(tau >> 6), n = (int)(tau & 63);
                int r0 = (win / 48) * 8 + (n >> 3) + SHIFTV; if (r0 >= HH) r0 -= HH;
                int c0 = (win % 48) * 8 + (n & 7)  + SHIFTV; if (c0 >= HH) c0 -= HH;
                const float* src = Xin + (long)(r0 * HH + c0) * CC + ch * 32 + kq * 4;
                float4 v4 = *(const float4*)src;
                uint2 u;
                u.x = packh2(v4.x, v4.y);
                u.y = packh2(v4.z, v4.w);
                *(uint2*)&smu[ch * 128 * HSA + row * HSA + kq * 2] = u;
            }
        }

        auto wt_of = [&](int w) -> const __half* {
            if (MODE == 0) return (w == 0) ? g_wtq : ((w == 1) ? g_wtk : g_wtv);
            return g_wt1;
        };
        auto nrb_of = [&](int w) -> int { return (MODE == 2) ? w * 192 : 0; };

        LOADB(wt_of(0), nrb_of(0), 0);
        STOREB(smu + RES_B_OFF);
        for (int s = 0; s < SEQ; s++) {
            int w = s / 6, kb = s % 6;
            if (s + 1 < SEQ) LOADB(wt_of((s + 1) / 6), nrb_of((s + 1) / 6), (s + 1) % 6);
            __syncthreads();
            MMA_CHUNK((uint32_t)(kb * 128 * HSA), (uint32_t)(RES_B_OFF + (s & 1) * 192 * HSA));
            if (kb == 5) EPI(w);
            if (s + 1 < SEQ) STOREB(smu + RES_B_OFF + ((s + 1) & 1) * 192 * HSA);
        }
    } else {
        const __half* Ah = (MODE == 1) ? g_ctx_h : g_mid_h;
        const __half* Wt = (MODE == 1) ? g_wtp : g_wt2;
        uint4 arh[2];
        auto LOADA = [&](int kb) {
#pragma unroll
            for (int i = 0; i < 2; i++) {
                int idx = tid + i * 256;
                int row = idx >> 2, kq4 = idx & 3;
                arh[i] = *(const uint4*)(Ah + ((long)tile * 128 + row) * KD + kb * 32 + kq4 * 8);
            }
        };
        auto STOREA = [&](uint32_t* A) {
#pragma unroll
            for (int i = 0; i < 2; i++) {
                int idx = tid + i * 256;
                int row = idx >> 2, kq4 = idx & 3;
                *(uint4*)&A[row * HSA + kq4 * 4] = arh[i];
            }
        };
        LOADA(0); LOADB(Wt, 0, 0);
        STOREA(smu + STR_A0); STOREB(smu + STR_B0);
        for (int kb = 0; kb < SEQ; kb++) {
            if (kb + 1 < SEQ) { LOADA(kb + 1); LOADB(Wt, 0, kb + 1); }
            __syncthreads();
            MMA_CHUNK((uint32_t)((kb & 1) ? STR_A1 : STR_A0),
                      (uint32_t)((kb & 1) ? STR_B1 : STR_B0));
            if (kb + 1 < SEQ) {
                STOREA(smu + (((kb + 1) & 1) ? STR_A1 : STR_A0));
                STOREB(smu + (((kb + 1) & 1) ? STR_B1 : STR_B0));
            }
        }
        EPI(0);
    }
}

// ======================= attention: fp16 q/k/v, post-MMA normalization =======================
__global__ void __launch_bounds__(128) k_attn(const float* __restrict__ logit_scale) {
    __shared__ float qs[64][36], ks[64][36], vs[64][36];
    __shared__ float ps[64][68];
    __shared__ float qinv[64], kinv[64];
    __shared__ int lab[64];
    __shared__ float sscale;

    int w = blockIdx.x, hd = blockIdx.y;
    int tid = threadIdx.x;
    int wid = tid >> 5, lane = tid & 31;
    int qr = lane >> 2, qc = lane & 3;
    int m0 = wid * 16;

    long base = ((long)(w * 6 + hd) * 64) * 32;
    auto load16 = [&](const __half* src, float (*dst)[36]) {
#pragma unroll
        for (int it = 0; it < 2; it++) {
            int s = tid + it * 128;
            int n = s >> 2, c8 = s & 3;
            uint4 u = *(const uint4*)(src + base + n * 32 + c8 * 8);
            const __half2* hp = (const __half2*)&u;
#pragma unroll
            for (int j = 0; j < 4; j++) {
                float2 f = __half22float2(hp[j]);
                dst[n][c8 * 8 + j * 2]     = f.x;
                dst[n][c8 * 8 + j * 2 + 1] = f.y;
            }
        }
    };
    load16(g_q_h, qs);
    load16(g_k_h, ks);
    load16(g_v_h, vs);
    if (tid == 0) sscale = __expf(fminf(logit_scale[hd], logf(100.f)));
    __syncthreads();

    if (tid < 64) {
        float s2 = 0.f;
#pragma unroll
        for (int d = 0; d < 32; d++) s2 += qs[tid][d] * qs[tid][d];
        qinv[tid] = 1.f / fmaxf(sqrtf(s2), 1e-12f);
        int r = (w / 48) * 8 + (tid >> 3);
        int c = (w % 48) * 8 + (tid & 7);
        int rr = (r < HH - WSZ) ? 0 : ((r < HH - SHIFTV) ? 1 : 2);
        int rc = (c < HH - WSZ) ? 0 : ((c < HH - SHIFTV) ? 1 : 2);
        lab[tid] = rr * 3 + rc;
    } else {
        int n = tid - 64;
        float s2 = 0.f;
#pragma unroll
        for (int d = 0; d < 32; d++) s2 += ks[n][d] * ks[n][d];
        kinv[n] = 1.f / fmaxf(sqrtf(s2), 1e-12f);
    }
    __syncthreads();

    float acc[8][4];
#pragma unroll
    for (int nt = 0; nt < 8; nt++)
#pragma unroll
        for (int t = 0; t < 4; t++) acc[nt][t] = 0.f;

    int i0 = m0 + qr, i1 = m0 + qr + 8;

#pragma unroll
    for (int kt = 0; kt < 4; kt++) {
        int k0 = kt * 8;
        uint32_t a0 = f2tf32(qs[i0][k0 + qc]);
        uint32_t a1 = f2tf32(qs[i1][k0 + qc]);
        uint32_t a2 = f2tf32(qs[i0][k0 + qc + 4]);
        uint32_t a3 = f2tf32(qs[i1][k0 + qc + 4]);
#pragma unroll
        for (int nt = 0; nt < 8; nt++) {
            int j = nt * 8 + qr;
            uint32_t b0 = f2tf32(ks[j][k0 + qc]);
            uint32_t b1 = f2tf32(ks[j][k0 + qc + 4]);
            mma_tf32(acc[nt][0], acc[nt][1], acc[nt][2], acc[nt][3],
                     a0, a1, a2, a3, b0, b1);
        }
    }

    float scl = sscale;
    float qi0 = qinv[i0] * scl, qi1 = qinv[i1] * scl;
    int labi0 = lab[i0], labi1 = lab[i1];
    const float* rpb = g_rpb + (hd << 12);
    float mx0 = -1e30f, mx1 = -1e30f;
#pragma unroll
    for (int nt = 0; nt < 8; nt++) {
#pragma unroll
        for (int e = 0; e < 2; e++) {
            int j = nt * 8 + 2 * qc + e;
            int labj = lab[j];
            float kj = kinv[j];
            float s0 = acc[nt][e] * qi0 * kj + rpb[(i0 << 6) + j];
            if (labi0 != labj) s0 -= 200.f;
            float s1 = acc[nt][2 + e] * qi1 * kj + rpb[(i1 << 6) + j];
            if (labi1 != labj) s1 -= 200.f;
            acc[nt][e] = s0; acc[nt][2 + e] = s1;
            mx0 = fmaxf(mx0, s0); mx1 = fmaxf(mx1, s1);
        }
    }
    mx0 = fmaxf(mx0, __shfl_xor_sync(0xffffffffu, mx0, 1));
    mx0 = fmaxf(mx0, __shfl_xor_sync(0xffffffffu, mx0, 2));
    mx1 = fmaxf(mx1, __shfl_xor_sync(0xffffffffu, mx1, 1));
    mx1 = fmaxf(mx1, __shfl_xor_sync(0xffffffffu, mx1, 2));
    float sum0 = 0.f, sum1 = 0.f;
#pragma unroll
    for (int nt = 0; nt < 8; nt++) {
#pragma unroll
        for (int e = 0; e < 2; e++) {
            float e0 = __expf(acc[nt][e] - mx0);
            float e1 = __expf(acc[nt][2 + e] - mx1);
            acc[nt][e] = e0; acc[nt][2 + e] = e1;
            sum0 += e0; sum1 += e1;
        }
    }
    sum0 += __shfl_xor_sync(0xffffffffu, sum0, 1);
    sum0 += __shfl_xor_sync(0xffffffffu, sum0, 2);
    sum1 += __shfl_xor_sync(0xffffffffu, sum1, 1);
    sum1 += __shfl_xor_sync(0xffffffffu, sum1, 2);
    float r0 = 1.f / sum0, r1 = 1.f / sum1;
#pragma unroll
    for (int nt = 0; nt < 8; nt++) {
        int j = nt * 8 + 2 * qc;
        ps[i0][j]     = acc[nt][0] * r0;
        ps[i0][j + 1] = acc[nt][1] * r0;
        ps[i1][j]     = acc[nt][2] * r1;
        ps[i1][j + 1] = acc[nt][3] * r1;
    }
    __syncwarp();

    float o[4][4];
#pragma unroll
    for (int nt = 0; nt < 4; nt++)
#pragma unroll
        for (int t = 0; t < 4; t++) o[nt][t] = 0.f;

#pragma unroll
    for (int kt = 0; kt < 8; kt++) {
        int k0 = kt * 8;
        uint32_t ah[4], al[4];
        split_tf32(ps[i0][k0 + qc],     ah[0], al[0]);
        split_tf32(ps[i1][k0 + qc],     ah[1], al[1]);
        split_tf32(ps[i0][k0 + qc + 4], ah[2], al[2]);
        split_tf32(ps[i1][k0 + qc + 4], ah[3], al[3]);
#pragma unroll
        for (int nt = 0; nt < 4; nt++) {
            int d = nt * 8 + qr;
            uint32_t bh0 = f2tf32(vs[k0 + qc][d]);
            uint32_t bh1 = f2tf32(vs[k0 + qc + 4][d]);
            mma_tf32(o[nt][0], o[nt][1], o[nt][2], o[nt][3],
                     ah[0], ah[1], ah[2], ah[3], bh0, bh1);
            mma_tf32(o[nt][0], o[nt][1], o[nt][2], o[nt][3],
                     al[0], al[1], al[2], al[3], bh0, bh1);
        }
    }

    __half* ob0 = g_ctx_h + ((long)(w * 64 + i0)) * CC + (hd << 5);
    __half* ob1 = g_ctx_h + ((long)(w * 64 + i1)) * CC + (hd << 5);
#pragma unroll
    for (int nt = 0; nt < 4; nt++) {
        int d = nt * 8 + 2 * qc;
        *(uint32_t*)(ob0 + d) = packh2(o[nt][0], o[nt][1]);
        *(uint32_t*)(ob1 + d) = packh2(o[nt][2], o[nt][3]);
    }
}

// ======================= LayerNorm + residual (LN2 only) =======================
__global__ void __launch_bounds__(256) k_ln_add(
    const float* __restrict__ xres, const float* __restrict__ xln,
    const float* __restrict__ g, const float* __restrict__ b,
    float* __restrict__ out) {
    int t = blockIdx.x * 8 + (threadIdx.x >> 5);
    int lane = threadIdx.x & 31;
    const float* row = xln + t * CC;
    float v[6];
    float sum = 0.f;
#pragma unroll
    for (int i = 0; i < 6; i++) { v[i] = row[lane + 32 * i]; sum += v[i]; }
#pragma unroll
    for (int o = 16; o > 0; o >>= 1) sum += __shfl_xor_sync(0xffffffffu, sum, o);
    float mu = sum * (1.0f / CC);
    float vs = 0.f;
#pragma unroll
    for (int i = 0; i < 6; i++) { float d = v[i] - mu; vs += d * d; }
#pragma unroll
    for (int o = 16; o > 0; o >>= 1) vs += __shfl_xor_sync(0xffffffffu, vs, o);
    float inv = rsqrtf(vs * (1.0f / CC) + 1e-5f);
#pragma unroll
    for (int i = 0; i < 6; i++) {
        int ch = lane + 32 * i;
        out[t * CC + ch] = xres[t * CC + ch] + (v[i] - mu) * inv * g[ch] + b[ch];
    }
}

// ======================= launch =======================
extern "C" void kernel_launch(void* const* d_in, const int* in_sizes, int n_in,
                              void* d_out, int out_size) {
    const float* hidden = (const float*)d_in[0];
    const float* q_w    = (const float*)d_in[1];
    const float* q_b    = (const float*)d_in[2];
    const float* k_w    = (const float*)d_in[3];
    const float* v_w    = (const float*)d_in[4];
    const float* v_b    = (const float*)d_in[5];
    const float* lscale = (const float*)d_in[6];
    const float* cpb_w1 = (const float*)d_in[7];
    const float* cpb_b1 = (const float*)d_in[8];
    const float* cpb_w2 = (const float*)d_in[9];
    const float* proj_w = (const float*)d_in[10];
    const float* proj_b = (const float*)d_in[11];
    const float* ln1_g  = (const float*)d_in[12];
    const float* ln1_b  = (const float*)d_in[13];
    const float* fc1_w  = (const float*)d_in[14];
    const float* fc1_b  = (const float*)d_in[15];
    const float* fc2_w  = (const float*)d_in[16];
    const float* fc2_b  = (const float*)d_in[17];
    const float* ln2_g  = (const float*)d_in[18];
    const float* ln2_b  = (const float*)d_in[19];
    float* out = (float*)d_out;

    float* gh; float* gxa; float* gmlp;
    cudaGetSymbolAddress((void**)&gh, g_h);
    cudaGetSymbolAddress((void**)&gxa, g_xattn);
    cudaGetSymbolAddress((void**)&gmlp, g_mlp);

    const int SMB_RES = RES_U32 * 4;   // 92160 B
    const int SMB_STR = STR_U32 * 4;   // 51200 B
    cudaFuncSetAttribute(k_g<0>, cudaFuncAttributeMaxDynamicSharedMemorySize, SMB_RES);
    cudaFuncSetAttribute(k_g<1>, cudaFuncAttributeMaxDynamicSharedMemorySize, SMB_STR);
    cudaFuncSetAttribute(k_g<2>, cudaFuncAttributeMaxDynamicSharedMemorySize, SMB_RES);
    cudaFuncSetAttribute(k_g<3>, cudaFuncAttributeMaxDynamicSharedMemorySize, SMB_STR);

    k_tr<<<1152, 256>>>(q_w, k_w, v_w, proj_w, fc1_w, fc2_w);
    k_cpb<<<225, 512>>>(cpb_w1, cpb_b1, cpb_w2);
    k_rpb<<<(NHEADS * NTOK * NTOK + 255) / 256, 256>>>();
    k_g<0><<<1152, 256, SMB_RES>>>(hidden, q_b, v_b, nullptr, nullptr, nullptr);
    k_attn<<<dim3(NWIN, NHEADS), 128>>>(lscale);
    k_g<1><<<1152, 256, SMB_STR>>>(nullptr, proj_b, nullptr, nullptr, nullptr, nullptr);
    k_g<2><<<1152, 256, SMB_RES>>>(gxa, fc1_b, nullptr, hidden, ln1_g, ln1_b);
    k_g<3><<<1152, 256, SMB_STR>>>(nullptr, fc2_b, nullptr, nullptr, nullptr, nullptr);
    k_ln_add<<<TT / 8, 256>>>(gh, gmlp, ln2_g, ln2_b, out);
}

// round 15
// speedup vs baseline: 1.1759x; 1.1759x over previous
#include <cuda_runtime.h>
#include <cuda_fp16.h>
#include <math.h>
#include <cstdint>

#define HH 384
#define CC 192
#define WSZ 8
#define SHIFTV 4
#define NHEADS 6
#define HDIM 32
#define NTOK 64
#define NWIN 2304
#define TT 147456

// -------- scratch (device globals) --------
__device__ __half g_q_h[NWIN*NHEADS*NTOK*HDIM];
__device__ __half g_k_h[NWIN*NHEADS*NTOK*HDIM];
__device__ __half g_v_h[NWIN*NHEADS*NTOK*HDIM];
__device__ __half g_ctx_h[TT*CC];
__device__ float g_xattn[TT*CC];
__device__ float g_h[TT*CC];
__device__ __half g_mid_h[TT*2*CC];
__device__ float g_mlp[TT*CC];
__device__ float g_rpb[NHEADS*NTOK*NTOK];
__device__ float g_btab[225*NHEADS];
// transposed fp16 weights [N, K] K-major
__device__ __half g_wtq[CC*CC];
__device__ __half g_wtk[CC*CC];
__device__ __half g_wtv[CC*CC];
__device__ __half g_wtp[CC*CC];
__device__ __half g_wt1[2*CC*CC];     // [384, 192]
__device__ __half g_wt2[CC*2*CC];     // [192, 384]

__device__ __forceinline__ uint32_t packh2(float lo, float hi) {
    __half2 h = __floats2half2_rn(lo, hi);
    return *reinterpret_cast<uint32_t*>(&h);
}

__device__ __forceinline__ void mma_f16(float& d0, float& d1, float& d2, float& d3,
                                        uint32_t a0, uint32_t a1, uint32_t a2, uint32_t a3,
                                        uint32_t b0, uint32_t b1) {
    asm volatile(
        "mma.sync.aligned.m16n8k16.row.col.f32.f16.f16.f32 "
        "{%0,%1,%2,%3}, {%4,%5,%6,%7}, {%8,%9}, {%0,%1,%2,%3};"
        : "+f"(d0), "+f"(d1), "+f"(d2), "+f"(d3)
        : "r"(a0), "r"(a1), "r"(a2), "r"(a3), "r"(b0), "r"(b1));
}

// ======================= weight transpose -> fp16 =======================
__global__ void k_tr(const float* __restrict__ q, const float* __restrict__ k,
                     const float* __restrict__ v, const float* __restrict__ p,
                     const float* __restrict__ f1, const float* __restrict__ f2) {
    int i = blockIdx.x * 256 + threadIdx.x;
    if (i < 36864)        g_wtq[(i % 192) * 192 + i / 192] = __float2half_rn(q[i]);
    else if (i < 73728)  { int j = i - 36864;  g_wtk[(j % 192) * 192 + j / 192] = __float2half_rn(k[j]); }
    else if (i < 110592) { int j = i - 73728;  g_wtv[(j % 192) * 192 + j / 192] = __float2half_rn(v[j]); }
    else if (i < 147456) { int j = i - 110592; g_wtp[(j % 192) * 192 + j / 192] = __float2half_rn(p[j]); }
    else if (i < 221184) { int j = i - 147456; g_wt1[(j % 384) * 192 + j / 384] = __float2half_rn(f1[j]); }
    else if (i < 294912) { int j = i - 221184; g_wt2[(j % 192) * 384 + j / 192] = __float2half_rn(f2[j]); }
}

// ======================= CPB / RPB =======================
__device__ __forceinline__ float cpb_coord(float x) {
    x = x / 7.0f * 8.0f;
    float s = (x > 0.f) ? 1.f : ((x < 0.f) ? -1.f : 0.f);
    return s * log2f(fabsf(x) + 1.0f) / log2f(8.0f);
}
__global__ void k_cpb(const float* __restrict__ w1, const float* __restrict__ b1,
                      const float* __restrict__ w2) {
    int row = blockIdx.x;
    int hh = threadIdx.x;
    float t0 = cpb_coord((float)(row / 15) - 7.0f);
    float t1 = cpb_coord((float)(row % 15) - 7.0f);
    float hv = t0 * w1[hh] + t1 * w1[512 + hh] + b1[hh];
    hv = fmaxf(hv, 0.f);
    __shared__ float red[512];
    for (int nh = 0; nh < 6; nh++) {
        red[hh] = hv * w2[hh * 6 + nh];
        __syncthreads();
        for (int s = 256; s > 0; s >>= 1) {
            if (hh < s) red[hh] += red[hh + s];
            __syncthreads();
        }
        if (hh == 0) g_btab[row * 6 + nh] = red[0];
        __syncthreads();
    }
}
__global__ void k_rpb() {
    int idx = blockIdx.x * 256 + threadIdx.x;
    if (idx >= NHEADS * NTOK * NTOK) return;
    int nh = idx >> 12;
    int ij = idx & 4095;
    int i = ij >> 6, j = ij & 63;
    int rel = ((i >> 3) - (j >> 3) + 7) * 15 + ((i & 7) - (j & 7) + 7);
    float b = g_btab[rel * 6 + nh];
    g_rpb[idx] = 16.0f / (1.0f + __expf(-b));
}

// ======================= fp16 GEMM with ldmatrix fragments (R13) =======================
#define HSA 20
#define RES_B_OFF (6*128*HSA)
#define RES_U32   (6*128*HSA + 2*192*HSA)
#define STR_A0 0
#define STR_A1 (128*HSA)
#define STR_B0 (2*128*HSA)
#define STR_B1 (2*128*HSA + 192*HSA)
#define STR_U32 (2*128*HSA + 2*192*HSA)

template <int MODE>
__global__ void __launch_bounds__(256, 1) k_g(const float* __restrict__ Xin,
                                              const float* __restrict__ bias_q,
                                              const float* __restrict__ bias_v) {
    constexpr bool RES = (MODE == 0 || MODE == 2);
    constexpr int KD  = (MODE == 3) ? 384 : 192;
    constexpr int NW  = (MODE == 0) ? 3 : ((MODE == 2) ? 2 : 1);
    constexpr int SEQ = RES ? NW * 6 : KD / 32;

    extern __shared__ uint32_t smu[];
    uint32_t sb = (uint32_t)__cvta_generic_to_shared(smu);
    int tid = threadIdx.x;
    int wid = tid >> 5, lane = tid & 31;
    int qr = lane >> 2, qc = lane & 3;
    int tile = blockIdx.x;

    int rb = (wid & 1) * 64;
    int nb0 = (wid >> 1) * 48;

    uint32_t a_row = (uint32_t)(rb + (lane & 15));
    uint32_t a_cadd = (uint32_t)((lane >> 4) * 4);
    uint32_t b_row = (uint32_t)(nb0 + (lane & 7) + ((lane >> 4) & 1) * 8);
    uint32_t b_cadd = (uint32_t)(((lane >> 3) & 1) * 4);

    float acc[4][6][4];
#pragma unroll
    for (int mf = 0; mf < 4; mf++)
#pragma unroll
        for (int nf = 0; nf < 6; nf++)
#pragma unroll
            for (int t = 0; t < 4; t++) acc[mf][nf][t] = 0.f;

    uint4 br[3];
    auto LOADB = [&](const __half* Wt, int nrow_base, int kb) {
#pragma unroll
        for (int i = 0; i < 3; i++) {
            int idx = tid + i * 256;
            int row = idx >> 2, kq4 = idx & 3;
            br[i] = *(const uint4*)(Wt + (long)(nrow_base + row) * KD + kb * 32 + kq4 * 8);
        }
    };
    auto STOREB = [&](uint32_t* B) {
#pragma unroll
        for (int i = 0; i < 3; i++) {
            int idx = tid + i * 256;
            int row = idx >> 2, kq4 = idx & 3;
            *(uint4*)&B[row * HSA + kq4 * 4] = br[i];
        }
    };

    auto MMA_CHUNK = [&](uint32_t Aoff, uint32_t Boff) {
#pragma unroll
        for (int g = 0; g < 2; g++) {
            uint32_t kof = g * 8;
            uint32_t a[4][4];
#pragma unroll
            for (int mf = 0; mf < 4; mf++) {
                uint32_t ad = sb + 4u * (Aoff + (a_row + mf * 16) * HSA + kof + a_cadd);
                asm volatile("ldmatrix.sync.aligned.m8n8.x4.shared.b16 {%0,%1,%2,%3}, [%4];"
                    : "=r"(a[mf][0]), "=r"(a[mf][1]), "=r"(a[mf][2]), "=r"(a[mf][3])
                    : "r"(ad));
            }
            uint32_t b[6][2];
#pragma unroll
            for (int p = 0; p < 3; p++) {
                uint32_t bd = sb + 4u * (Boff + (b_row + p * 16) * HSA + kof + b_cadd);
                asm volatile("ldmatrix.sync.aligned.m8n8.x4.shared.b16 {%0,%1,%2,%3}, [%4];"
                    : "=r"(b[2*p][0]), "=r"(b[2*p][1]), "=r"(b[2*p+1][0]), "=r"(b[2*p+1][1])
                    : "r"(bd));
            }
#pragma unroll
            for (int nf = 0; nf < 6; nf++)
#pragma unroll
                for (int mf = 0; mf < 4; mf++)
                    mma_f16(acc[mf][nf][0], acc[mf][nf][1], acc[mf][nf][2], acc[mf][nf][3],
                            a[mf][0], a[mf][1], a[mf][2], a[mf][3], b[nf][0], b[nf][1]);
        }
    };

    auto EPI = [&](int w) {
        const float* bias;
        if (MODE == 0)      bias = (w == 0) ? bias_q : ((w == 1) ? nullptr : bias_v);
        else                bias = bias_q;
#pragma unroll
        for (int mf = 0; mf < 4; mf++) {
#pragma unroll
            for (int t = 0; t < 2; t++) {
                int rloc = rb + mf * 16 + qr + t * 8;
                long tau = (long)tile * 128 + rloc;
                int win = (int)(tau >> 6), n = (int)(tau & 63);
#pragma unroll
                for (int nf = 0; nf < 6; nf++) {
                    int cloc = nb0 + nf * 8 + qc * 2;
                    float vx = acc[mf][nf][t * 2 + 0];
                    float vy = acc[mf][nf][t * 2 + 1];
                    if (MODE == 0) {
                        if (bias) { vx += bias[cloc]; vy += bias[cloc + 1]; }
                        int head = cloc >> 5, d = cloc & 31;
                        long off = (((long)(win * 6 + head) * 64 + n) << 5) + d;
                        __half* dst = (w == 0) ? g_q_h : ((w == 1) ? g_k_h : g_v_h);
                        *(uint32_t*)(dst + off) = packh2(vx, vy);
                    } else if (MODE == 1) {
                        vx += bias[cloc]; vy += bias[cloc + 1];
                        int r0 = (win / 48) * 8 + (n >> 3) + SHIFTV; if (r0 >= HH) r0 -= HH;
                        int c0 = (win % 48) * 8 + (n & 7)  + SHIFTV; if (c0 >= HH) c0 -= HH;
                        float* dst = g_xattn + (long)(r0 * HH + c0) * CC + cloc;
                        *(float2*)dst = make_float2(vx, vy);
                    } else if (MODE == 2) {
                        int col = w * 192 + cloc;
                        vx += bias[col]; vy += bias[col + 1];
                        vx = 0.5f * vx * (1.0f + erff(vx * 0.70710678118654752f));
                        vy = 0.5f * vy * (1.0f + erff(vy * 0.70710678118654752f));
                        *(uint32_t*)(g_mid_h + tau * 384 + col) = packh2(vx, vy);
                    } else {
                        vx += bias[cloc]; vy += bias[cloc + 1];
                        float* dst = g_mlp + tau * CC + cloc;
                        *(float2*)dst = make_float2(vx, vy);
                    }
                }
            }
        }
        if (RES && w + 1 < NW) {
#pragma unroll
            for (int mf = 0; mf < 4; mf++)
#pragma unroll
                for (int nf = 0; nf < 6; nf++)
#pragma unroll
                    for (int t = 0; t < 4; t++) acc[mf][nf][t] = 0.f;
        }
    };

    if (RES) {
#pragma unroll
        for (int i = 0; i < 24; i++) {
            int idx = tid + i * 256;
            int ch = idx >> 10, t2 = idx & 1023;
            int row = t2 >> 3, kq = t2 & 7;
            const float* src;
            long tau = (long)tile * 128 + row;
            if (MODE == 0) {
                int win = (int)(tau >> 6), n = (int)(tau & 63);
                int r0 = (win / 48) * 8 + (n >> 3) + SHIFTV; if (r0 >= HH) r0 -= HH;
                int c0 = (win % 48) * 8 + (n & 7)  + SHIFTV; if (c0 >= HH) c0 -= HH;
                src = Xin + (long)(r0 * HH + c0) * CC + ch * 32 + kq * 4;
            } else {
                src = g_h + tau * 192 + ch * 32 + kq * 4;
            }
            float4 v4 = *(const float4*)src;
            uint2 u;
            u.x = packh2(v4.x, v4.y);
            u.y = packh2(v4.z, v4.w);
            *(uint2*)&smu[ch * 128 * HSA + row * HSA + kq * 2] = u;
        }

        auto wt_of = [&](int w) -> const __half* {
            if (MODE == 0) return (w == 0) ? g_wtq : ((w == 1) ? g_wtk : g_wtv);
            return g_wt1;
        };
        auto nrb_of = [&](int w) -> int { return (MODE == 2) ? w * 192 : 0; };

        LOADB(wt_of(0), nrb_of(0), 0);
        STOREB(smu + RES_B_OFF);
        for (int s = 0; s < SEQ; s++) {
            int w = s / 6, kb = s % 6;
            if (s + 1 < SEQ) LOADB(wt_of((s + 1) / 6), nrb_of((s + 1) / 6), (s + 1) % 6);
            __syncthreads();
            MMA_CHUNK((uint32_t)(kb * 128 * HSA), (uint32_t)(RES_B_OFF + (s & 1) * 192 * HSA));
            if (kb == 5) EPI(w);
            if (s + 1 < SEQ) STOREB(smu + RES_B_OFF + ((s + 1) & 1) * 192 * HSA);
        }
    } else {
        const __half* Ah = (MODE == 1) ? g_ctx_h : g_mid_h;
        const __half* Wt = (MODE == 1) ? g_wtp : g_wt2;
        uint4 arh[2];
        auto LOADA = [&](int kb) {
#pragma unroll
            for (int i = 0; i < 2; i++) {
                int idx = tid + i * 256;
                int row = idx >> 2, kq4 = idx & 3;
                arh[i] = *(const uint4*)(Ah + ((long)tile * 128 + row) * KD + kb * 32 + kq4 * 8);
            }
        };
        auto STOREA = [&](uint32_t* A) {
#pragma unroll
            for (int i = 0; i < 2; i++) {
                int idx = tid + i * 256;
                int row = idx >> 2, kq4 = idx & 3;
                *(uint4*)&A[row * HSA + kq4 * 4] = arh[i];
            }
        };
        LOADA(0); LOADB(Wt, 0, 0);
        STOREA(smu + STR_A0); STOREB(smu + STR_B0);
        for (int kb = 0; kb < SEQ; kb++) {
            if (kb + 1 < SEQ) { LOADA(kb + 1); LOADB(Wt, 0, kb + 1); }
            __syncthreads();
            MMA_CHUNK((uint32_t)((kb & 1) ? STR_A1 : STR_A0),
                      (uint32_t)((kb & 1) ? STR_B1 : STR_B0));
            if (kb + 1 < SEQ) {
                STOREA(smu + (((kb + 1) & 1) ? STR_A1 : STR_A0));
                STOREB(smu + (((kb + 1) & 1) ? STR_B1 : STR_B0));
            }
        }
        EPI(0);
    }
}

// ======================= attention: all-fp16 MMA =======================
// q/k stay packed fp16 in smem (u32 stride 20); QK^T and P·V use m16n8k16 f16
// with fp32 accumulation. fp16 products are exact -> QK^T numerically matches
// the previous tf32 path; only P's fp16 rounding is new.
__global__ void __launch_bounds__(128) k_attn(const float* __restrict__ logit_scale) {
    __shared__ uint32_t qsu[64*20], ksu[64*20];
    __shared__ __half vsh[64][40];
    __shared__ uint32_t psu[64*36];
    __shared__ float qinv[64], kinv[64];
    __shared__ int lab[64];
    __shared__ float sscale;

    int w = blockIdx.x, hd = blockIdx.y;
    int tid = threadIdx.x;
    int wid = tid >> 5, lane = tid & 31;
    int qr = lane >> 2, qc = lane & 3;
    int m0 = wid * 16;

    long base = ((long)(w * 6 + hd) * 64) * 32;
#pragma unroll
    for (int it = 0; it < 2; it++) {
        int s = tid + it * 128;       // 0..255 uint4 slots
        int n = s >> 2, c4 = s & 3;
        *(uint4*)&qsu[n * 20 + c4 * 4] = *(const uint4*)(g_q_h + base + n * 32 + c4 * 8);
        *(uint4*)&ksu[n * 20 + c4 * 4] = *(const uint4*)(g_k_h + base + n * 32 + c4 * 8);
        *(uint4*)&vsh[n][c4 * 8]       = *(const uint4*)(g_v_h + base + n * 32 + c4 * 8);
    }
    if (tid == 0) sscale = __expf(fminf(logit_scale[hd], logf(100.f)));
    __syncthreads();

    if (tid < 64) {
        float s2 = 0.f;
#pragma unroll
        for (int i = 0; i < 16; i++) {
            float2 f = __half22float2(*(const __half2*)&qsu[tid * 20 + i]);
            s2 += f.x * f.x + f.y * f.y;
        }
        qinv[tid] = 1.f / fmaxf(sqrtf(s2), 1e-12f);
        int r = (w / 48) * 8 + (tid >> 3);
        int c = (w % 48) * 8 + (tid & 7);
        int rr = (r < HH - WSZ) ? 0 : ((r < HH - SHIFTV) ? 1 : 2);
        int rc = (c < HH - WSZ) ? 0 : ((c < HH - SHIFTV) ? 1 : 2);
        lab[tid] = rr * 3 + rc;
    } else {
        int n = tid - 64;
        float s2 = 0.f;
#pragma unroll
        for (int i = 0; i < 16; i++) {
            float2 f = __half22float2(*(const __half2*)&ksu[n * 20 + i]);
            s2 += f.x * f.x + f.y * f.y;
        }
        kinv[n] = 1.f / fmaxf(sqrtf(s2), 1e-12f);
    }
    __syncthreads();

    // ---- raw QK^T: fp16 MMA, 2 k16 groups x 8 n-tiles ----
    float acc[8][4];
#pragma unroll
    for (int nt = 0; nt < 8; nt++)
#pragma unroll
        for (int t = 0; t < 4; t++) acc[nt][t] = 0.f;

    int i0 = m0 + qr, i1 = m0 + qr + 8;

#pragma unroll
    for (int g = 0; g < 2; g++) {
        int kof = g * 8;
        uint32_t a0 = qsu[i0 * 20 + kof + qc];
        uint32_t a1 = qsu[i1 * 20 + kof + qc];
        uint32_t a2 = qsu[i0 * 20 + kof + qc + 4];
        uint32_t a3 = qsu[i1 * 20 + kof + qc + 4];
#pragma unroll
        for (int nt = 0; nt < 8; nt++) {
            int j = nt * 8 + qr;
            uint32_t b0 = ksu[j * 20 + kof + qc];
            uint32_t b1 = ksu[j * 20 + kof + qc + 4];
            mma_f16(acc[nt][0], acc[nt][1], acc[nt][2], acc[nt][3],
                    a0, a1, a2, a3, b0, b1);
        }
    }

    // ---- normalize + bias + mask + softmax ----
    float scl = sscale;
    float qi0 = qinv[i0] * scl, qi1 = qinv[i1] * scl;
    int labi0 = lab[i0], labi1 = lab[i1];
    const float* rpb = g_rpb + (hd << 12);
    float mx0 = -1e30f, mx1 = -1e30f;
#pragma unroll
    for (int nt = 0; nt < 8; nt++) {
#pragma unroll
        for (int e = 0; e < 2; e++) {
            int j = nt * 8 + 2 * qc + e;
            int labj = lab[j];
            float kj = kinv[j];
            float s0 = acc[nt][e] * qi0 * kj + rpb[(i0 << 6) + j];
            if (labi0 != labj) s0 -= 200.f;
            float s1 = acc[nt][2 + e] * qi1 * kj + rpb[(i1 << 6) + j];
            if (labi1 != labj) s1 -= 200.f;
            acc[nt][e] = s0; acc[nt][2 + e] = s1;
            mx0 = fmaxf(mx0, s0); mx1 = fmaxf(mx1, s1);
        }
    }
    mx0 = fmaxf(mx0, __shfl_xor_sync(0xffffffffu, mx0, 1));
    mx0 = fmaxf(mx0, __shfl_xor_sync(0xffffffffu, mx0, 2));
    mx1 = fmaxf(mx1, __shfl_xor_sync(0xffffffffu, mx1, 1));
    mx1 = fmaxf(mx1, __shfl_xor_sync(0xffffffffu, mx1, 2));
    float sum0 = 0.f, sum1 = 0.f;
#pragma unroll
    for (int nt = 0; nt < 8; nt++) {
#pragma unroll
        for (int e = 0; e < 2; e++) {
            float e0 = __expf(acc[nt][e] - mx0);
            float e1 = __expf(acc[nt][2 + e] - mx1);
            acc[nt][e] = e0; acc[nt][2 + e] = e1;
            sum0 += e0; sum1 += e1;
        }
    }
    sum0 += __shfl_xor_sync(0xffffffffu, sum0, 1);
    sum0 += __shfl_xor_sync(0xffffffffu, sum0, 2);
    sum1 += __shfl_xor_sync(0xffffffffu, sum1, 1);
    sum1 += __shfl_xor_sync(0xffffffffu, sum1, 2);
    float r0 = 1.f / sum0, r1 = 1.f / sum1;
    // store probs as packed fp16 (u32 per adjacent j-pair)
#pragma unroll
    for (int nt = 0; nt < 8; nt++) {
        psu[i0 * 36 + nt * 4 + qc] = packh2(acc[nt][0] * r0, acc[nt][1] * r0);
        psu[i1 * 36 + nt * 4 + qc] = packh2(acc[nt][2] * r1, acc[nt][3] * r1);
    }
    __syncwarp();

    // ---- ctx = P @ V: fp16 MMA, 4 k16 groups x 4 n-tiles ----
    float o[4][4];
#pragma unroll
    for (int nt = 0; nt < 4; nt++)
#pragma unroll
        for (int t = 0; t < 4; t++) o[nt][t] = 0.f;

#pragma unroll
    for (int kt = 0; kt < 4; kt++) {
        int kb = kt * 8;                 // u32 base within P row
        uint32_t a0 = psu[i0 * 36 + kb + qc];
        uint32_t a1 = psu[i1 * 36 + kb + qc];
        uint32_t a2 = psu[i0 * 36 + kb + qc + 4];
        uint32_t a3 = psu[i1 * 36 + kb + qc + 4];
        int j0 = kt * 16 + 2 * qc;
#pragma unroll
        for (int nt = 0; nt < 4; nt++) {
            int d = nt * 8 + qr;
            __half2 h0, h1;
            h0.x = vsh[j0][d];     h0.y = vsh[j0 + 1][d];
            h1.x = vsh[j0 + 8][d]; h1.y = vsh[j0 + 9][d];
            mma_f16(o[nt][0], o[nt][1], o[nt][2], o[nt][3],
                    a0, a1, a2, a3,
                    *(uint32_t*)&h0, *(uint32_t*)&h1);
        }
    }

    __half* ob0 = g_ctx_h + ((long)(w * 64 + i0)) * CC + (hd << 5);
    __half* ob1 = g_ctx_h + ((long)(w * 64 + i1)) * CC + (hd << 5);
#pragma unroll
    for (int nt = 0; nt < 4; nt++) {
        int d = nt * 8 + 2 * qc;
        *(uint32_t*)(ob0 + d) = packh2(o[nt][0], o[nt][1]);
        *(uint32_t*)(ob1 + d) = packh2(o[nt][2], o[nt][3]);
    }
}

// ======================= LayerNorm + residual =======================
__global__ void __launch_bounds__(256) k_ln_add(
    const float* __restrict__ xres, const float* __restrict__ xln,
    const float* __restrict__ g, const float* __restrict__ b,
    float* __restrict__ out) {
    int t = blockIdx.x * 8 + (threadIdx.x >> 5);
    int lane = threadIdx.x & 31;
    const float* row = xln + t * CC;
    float v[6];
    float sum = 0.f;
#pragma unroll
    for (int i = 0; i < 6; i++) { v[i] = row[lane + 32 * i]; sum += v[i]; }
#pragma unroll
    for (int o = 16; o > 0; o >>= 1) sum += __shfl_xor_sync(0xffffffffu, sum, o);
    float mu = sum * (1.0f / CC);
    float vs = 0.f;
#pragma unroll
    for (int i = 0; i < 6; i++) { float d = v[i] - mu; vs += d * d; }
#pragma unroll
    for (int o = 16; o > 0; o >>= 1) vs += __shfl_xor_sync(0xffffffffu, vs, o);
    float inv = rsqrtf(vs * (1.0f / CC) + 1e-5f);
#pragma unroll
    for (int i = 0; i < 6; i++) {
        int ch = lane + 32 * i;
        out[t * CC + ch] = xres[t * CC + ch] + (v[i] - mu) * inv * g[ch] + b[ch];
    }
}

// ======================= launch =======================
extern "C" void kernel_launch(void* const* d_in, const int* in_sizes, int n_in,
                              void* d_out, int out_size) {
    const float* hidden = (const float*)d_in[0];
    const float* q_w    = (const float*)d_in[1];
    const float* q_b    = (const float*)d_in[2];
    const float* k_w    = (const float*)d_in[3];
    const float* v_w    = (const float*)d_in[4];
    const float* v_b    = (const float*)d_in[5];
    const float* lscale = (const float*)d_in[6];
    const float* cpb_w1 = (const float*)d_in[7];
    const float* cpb_b1 = (const float*)d_in[8];
    const float* cpb_w2 = (const float*)d_in[9];
    const float* proj_w = (const float*)d_in[10];
    const float* proj_b = (const float*)d_in[11];
    const float* ln1_g  = (const float*)d_in[12];
    const float* ln1_b  = (const float*)d_in[13];
    const float* fc1_w  = (const float*)d_in[14];
    const float* fc1_b  = (const float*)d_in[15];
    const float* fc2_w  = (const float*)d_in[16];
    const float* fc2_b  = (const float*)d_in[17];
    const float* ln2_g  = (const float*)d_in[18];
    const float* ln2_b  = (const float*)d_in[19];
    float* out = (float*)d_out;

    float* gh; float* gxa; float* gmlp;
    cudaGetSymbolAddress((void**)&gh, g_h);
    cudaGetSymbolAddress((void**)&gxa, g_xattn);
    cudaGetSymbolAddress((void**)&gmlp, g_mlp);

    const int SMB_RES = RES_U32 * 4;   // 92160 B
    const int SMB_STR = STR_U32 * 4;   // 51200 B
    cudaFuncSetAttribute(k_g<0>, cudaFuncAttributeMaxDynamicSharedMemorySize, SMB_RES);
    cudaFuncSetAttribute(k_g<1>, cudaFuncAttributeMaxDynamicSharedMemorySize, SMB_STR);
    cudaFuncSetAttribute(k_g<2>, cudaFuncAttributeMaxDynamicSharedMemorySize, SMB_RES);
    cudaFuncSetAttribute(k_g<3>, cudaFuncAttributeMaxDynamicSharedMemorySize, SMB_STR);

    k_tr<<<1152, 256>>>(q_w, k_w, v_w, proj_w, fc1_w, fc2_w);
    k_cpb<<<225, 512>>>(cpb_w1, cpb_b1, cpb_w2);
    k_rpb<<<(NHEADS * NTOK * NTOK + 255) / 256, 256>>>();
    k_g<0><<<1152, 256, SMB_RES>>>(hidden, q_b, v_b);
    k_attn<<<dim3(NWIN, NHEADS), 128>>>(lscale);
    k_g<1><<<1152, 256, SMB_STR>>>(nullptr, proj_b, nullptr);
    k_ln_add<<<TT / 8, 256>>>(hidden, gxa, ln1_g, ln1_b, gh);
    k_g<2><<<1152, 256, SMB_RES>>>(nullptr, fc1_b, nullptr);
    k_g<3><<<1152, 256, SMB_STR>>>(nullptr, fc2_b, nullptr);
    k_ln_add<<<TT / 8, 256>>>(gh, gmlp, ln2_g, ln2_b, out);
}